// round 11
// baseline (speedup 1.0000x reference)
#include <cuda_runtime.h>
#include <math.h>

// DifferentiableICP: B=32, N=M=2048, 5 soft-ICP iterations.
// R10: hybrid exp. We sit ~3-5% off the MUFU.EX2 roofline (32 cyc/pair), so
//      lower the floor: 1 of every 4 packed exp-pairs is computed as a
//      polynomial exp2 on the (40%-idle) FMA pipe + ALU exponent-insert.
//      New balance per 4 pairs: MUFU 112 cyc, fma 98, issue ~80 -> 28 cyc/pair
//      (-12.5%). Fixed (j==3,k==1) assignment -> deterministic. Poly err ~1e-7.
//      launch_bounds(128,7): only 7 CTAs/SM ever resident (1024/148), so the
//      reg cap rises 64->73 and the +10 poly regs don't spill.
// Structure unchanged from R9: init + 5 iter (update folded into head) + final.

#define BB 32
#define NN 2048
#define MM 2048
#define ITERS 5
#define CHUNKS 32                    // CTAs per batch
#define ROWS_PER_CTA (NN / CHUNKS)   // 64
#define RPT 2                        // rows per thread
#define MSPLIT 4                     // warps per CTA == M segments
#define TPB (32 * MSPLIT)            // 128
#define NPAIR (MM / 2)               // 1024 packed target pairs
#define SEGPAIRS (NPAIR / MSPLIT)    // 256 pairs per segment

typedef unsigned long long ull;

// Scratch (allocation-free rule: __device__ globals)
__device__ ulonglong2 g_uv2[BB][NPAIR]; // packed ((2L2E*tx),(2L2E*ty)) pairs
__device__ ull        g_w2[BB][NPAIR];  // packed (-L2E*|t|^2) pairs
__device__ float      g_Tbuf[2][BB][4]; // (cos,sin,tx,ty), double-buffered
__device__ float      g_part[BB][CHUNKS][8];

// ---- packed f32x2 helpers (PTX-only; ptxas never auto-fuses FFMA2) --------
__device__ __forceinline__ ull fma2(ull a, ull b, ull c) {
    ull d; asm("fma.rn.f32x2 %0, %1, %2, %3;" : "=l"(d) : "l"(a), "l"(b), "l"(c));
    return d;
}
__device__ __forceinline__ ull add2(ull a, ull b) {
    ull d; asm("add.rn.f32x2 %0, %1, %2;" : "=l"(d) : "l"(a), "l"(b));
    return d;
}
__device__ __forceinline__ ull pack2(float lo, float hi) {
    ull d; asm("mov.b64 %0, {%1, %2};" : "=l"(d) : "f"(lo), "f"(hi));
    return d;
}
__device__ __forceinline__ void unpack2(ull v, float& lo, float& hi) {
    asm("mov.b64 {%0, %1}, %2;" : "=f"(lo), "=f"(hi) : "l"(v));
}
__device__ __forceinline__ float ex2f(float x) {
    float e; asm("ex2.approx.ftz.f32 %0, %1;" : "=f"(e) : "f"(x));
    return e;
}

// Polynomial exp2 on a packed pair: fma-pipe range reduction (magic round),
// scalar FFMA Horner (Cephes degree-6, rel err ~1e-7), ALU exponent insert
// with clamp (handles y down to ~-175 without bit-wrap; 2^-120 ~ 0 anyway).
__device__ __forceinline__ ull exp2_poly2(ull y2) {
    const ull MAGIC2 = 0x4B4000004B400000ull;  // (12582912.f, 12582912.f) = 1.5*2^23
    const ull NEG1   = 0xBF800000BF800000ull;  // (-1.f, -1.f)
    const ull t2  = add2(y2, MAGIC2);          // t = y + magic  (n in mantissa)
    const ull nf2 = fma2(MAGIC2, NEG1, t2);    // n = t - magic  (float, = RN(y))
    const ull r2  = fma2(nf2, NEG1, y2);       // r = y - n, r in [-0.5, 0.5]
    float r0, r1; unpack2(r2, r0, r1);
    float t0, t1; unpack2(t2, t0, t1);

    float w0 = fmaf(1.535336188319500e-4f, r0, 1.339887440266574e-3f);
    w0 = fmaf(w0, r0, 9.618437357674640e-3f);
    w0 = fmaf(w0, r0, 5.550332471162809e-2f);
    w0 = fmaf(w0, r0, 2.402264791363012e-1f);
    w0 = fmaf(w0, r0, 6.931472028550421e-1f);
    w0 = fmaf(w0, r0, 1.0f);
    float w1 = fmaf(1.535336188319500e-4f, r1, 1.339887440266574e-3f);
    w1 = fmaf(w1, r1, 9.618437357674640e-3f);
    w1 = fmaf(w1, r1, 5.550332471162809e-2f);
    w1 = fmaf(w1, r1, 2.402264791363012e-1f);
    w1 = fmaf(w1, r1, 6.931472028550421e-1f);
    w1 = fmaf(w1, r1, 1.0f);

    int n0 = __float_as_int(t0) - 0x4B400000;  // integer n
    int n1 = __float_as_int(t1) - 0x4B400000;
    n0 = max(n0, -120);                        // keep exponent field positive
    n1 = max(n1, -120);
    const float e0 = __int_as_float(__float_as_int(w0) + (n0 << 23));
    const float e1 = __int_as_float(__float_as_int(w1) + (n1 << 23));
    return pack2(e0, e1);
}

// ---------------------------------------------------------------------------
// Shared update math: given the 8 reduced sums p[] and T_old, produce T_new.
// R_delta = V @ U^T (SVD of H) == orthogonal polar factor of H^T, closed form.
// MUST be called with identical inputs everywhere it's used (bit-identical).
// ---------------------------------------------------------------------------
__device__ __forceinline__ void icp_compose(const float p[8],
                                            float cc, float ss, float ttx, float tty,
                                            float& c2, float& s2, float& tx2, float& ty2) {
    const float invN = 1.0f / (float)NN;
    const float csx = p[0] * invN, csy = p[1] * invN;
    const float ctx = p[2] * invN, cty = p[3] * invN;

    const float h00 = p[4] - p[0] * p[2] * invN;
    const float h01 = p[5] - p[0] * p[3] * invN;
    const float h10 = p[6] - p[1] * p[2] * invN;
    const float h11 = p[7] - p[1] * p[3] * invN;

    const float E  = 0.5f * (h00 + h11);
    const float F  = 0.5f * (h00 - h11);
    const float G  = 0.5f * (h01 + h10);
    const float Hh = 0.5f * (h01 - h10);
    const float det = h00 * h11 - h01 * h10;

    float r00, r01, r10, r11;
    if (det >= 0.0f) {           // rotation branch
        float iq = rsqrtf(E * E + Hh * Hh);
        r00 =  E * iq;  r01 = -Hh * iq;
        r10 = Hh * iq;  r11 =  E * iq;
    } else {                      // reflection branch
        float ir = rsqrtf(F * F + G * G);
        r00 =  F * ir;  r01 =  G * ir;
        r10 =  G * ir;  r11 = -F * ir;
    }

    const float ih = rsqrtf(r00 * r00 + r10 * r10);
    const float cD = r00 * ih;
    const float sD = r10 * ih;
    const float tDx = ctx - (r00 * csx + r01 * csy);
    const float tDy = cty - (r10 * csx + r11 * csy);

    c2  = cD * cc - sD * ss;
    s2  = sD * cc + cD * ss;
    tx2 = cD * ttx - sD * tty + tDx;
    ty2 = sD * ttx + cD * tty + tDy;
}

// ---------------------------------------------------------------------------
// Init: paired, log2e-folded target constants + initial transform (buf 0).
// ---------------------------------------------------------------------------
__global__ void icp_init_kernel(const float* __restrict__ target,
                                const float* __restrict__ init_t) {
    int g = blockIdx.x * blockDim.x + threadIdx.x;
    if (g < BB * NPAIR) {
        int b = g >> 10, p = g & (NPAIR - 1);
        float4 f = reinterpret_cast<const float4*>(target)[(size_t)b * NPAIR + p];
        const float L2E = 1.4426950408889634f;
        ulonglong2 uv;
        uv.x = pack2(2.0f * L2E * f.x, 2.0f * L2E * f.z);
        uv.y = pack2(2.0f * L2E * f.y, 2.0f * L2E * f.w);
        g_uv2[b][p] = uv;
        g_w2[b][p]  = pack2(-L2E * (f.x * f.x + f.y * f.y),
                            -L2E * (f.z * f.z + f.w * f.w));
    }
    if (g < BB) {
        float th = init_t[g * 3 + 0];
        g_Tbuf[0][g][0] = cosf(th);
        g_Tbuf[0][g][1] = sinf(th);
        g_Tbuf[0][g][2] = init_t[g * 3 + 1];
        g_Tbuf[0][g][3] = init_t[g * 3 + 2];
    }
}

// ---------------------------------------------------------------------------
// Iter kernel `it` (0..4). grid = BB*CHUNKS = 1024 CTAs, block = 128.
// Head (it>0): every CTA redundantly reduces previous g_part and composes
//   T_it from g_Tbuf[it&1]; chunk0 persists T_it to g_Tbuf[(it+1)&1].
// Body: hybrid MUFU/poly softmax mainloop writing this iteration's g_part.
// ---------------------------------------------------------------------------
__global__ void __launch_bounds__(TPB, 7)
icp_iter_kernel(const float* __restrict__ source, int it) {
    __shared__ ulonglong2 sUV[NPAIR];                     // 16 KB
    __shared__ ull        sW[NPAIR];                      // 8 KB
    __shared__ float4     sRow[MSPLIT - 1][ROWS_PER_CTA]; // 3 KB

    const int b     = blockIdx.x >> 5;
    const int chunk = blockIdx.x & 31;
    const int tid   = threadIdx.x;
    const int lane  = tid & 31;
    const int warp  = tid >> 5;          // == M-segment

    // Stage paired target constants (coalesced 16B/8B loads)
    for (int i = tid; i < NPAIR; i += TPB) {
        sUV[i] = g_uv2[b][i];
        sW[i]  = g_w2[b][i];
    }

    // ---- compute this iteration's transform (redundant per warp) ----
    const int rd = it & 1;
    float c, s, tx, ty;
    {
        const float cc  = g_Tbuf[rd][b][0];
        const float ss  = g_Tbuf[rd][b][1];
        const float ttx = g_Tbuf[rd][b][2];
        const float tty = g_Tbuf[rd][b][3];
        if (it == 0) {
            c = cc; s = ss; tx = ttx; ty = tty;
        } else {
            // lane == chunk index: reduce previous iteration's partials
            float p[8];
            #pragma unroll
            for (int k = 0; k < 8; ++k) p[k] = g_part[b][lane][k];
            #pragma unroll
            for (int off = 16; off; off >>= 1)
                #pragma unroll
                for (int k = 0; k < 8; ++k)
                    p[k] += __shfl_xor_sync(0xFFFFFFFFu, p[k], off);
            icp_compose(p, cc, ss, ttx, tty, c, s, tx, ty);
        }
        // persist T_it for the next kernel (double-buffered: no read/write race)
        if (chunk == 0 && tid == 0) {
            g_Tbuf[rd ^ 1][b][0] = c;
            g_Tbuf[rd ^ 1][b][1] = s;
            g_Tbuf[rd ^ 1][b][2] = tx;
            g_Tbuf[rd ^ 1][b][3] = ty;
        }
    }

    // st = R*source + t for this thread's 2 rows
    float sx[RPT], sy[RPT];
    ull sx2[RPT], sy2[RPT];
    #pragma unroll
    for (int k = 0; k < RPT; ++k) {
        const int row = chunk * ROWS_PER_CTA + lane + 32 * k;
        const float2 sv = reinterpret_cast<const float2*>(source)[(size_t)b * NN + row];
        sx[k] = c * sv.x - s * sv.y + tx;
        sy[k] = s * sv.x + c * sv.y + ty;
        sx2[k] = pack2(sx[k], sx[k]);
        sy2[k] = pack2(sy[k], sy[k]);
    }

    __syncthreads();

    // Hybrid single-pass softmax-weighted sums: 2 LDS/pair, reused x2 rows.
    // Per group of 4 pairs: 7 packed exps via MUFU ex2, 1 via fma-pipe poly.
    ull se2[RPT], au2[RPT], av2[RPT];
    #pragma unroll
    for (int k = 0; k < RPT; ++k) { se2[k] = 0ull; au2[k] = 0ull; av2[k] = 0ull; }

    const int p0 = warp * SEGPAIRS;
    #pragma unroll 1
    for (int g = p0; g < p0 + SEGPAIRS; g += 4) {
        #pragma unroll
        for (int j = 0; j < 4; ++j) {
            const ulonglong2 uv = sUV[g + j];
            const ull u2 = uv.x;
            const ull v2 = uv.y;
            const ull w2 = sW[g + j];
            #pragma unroll
            for (int k = 0; k < RPT; ++k) {
                ull y2 = fma2(sx2[k], u2, w2);
                y2 = fma2(sy2[k], v2, y2);
                ull e2;
                if (j == 3 && k == 1) {
                    e2 = exp2_poly2(y2);            // fma/alu-pipe exp
                } else {
                    float y0, y1; unpack2(y2, y0, y1);
                    e2 = pack2(ex2f(y0), ex2f(y1)); // MUFU exp
                }
                se2[k] = add2(se2[k], e2);
                au2[k] = fma2(e2, u2, au2[k]);
                av2[k] = fma2(e2, v2, av2[k]);
            }
        }
    }

    // Horizontal add of the packed halves (fixed order: lo + hi)
    float se[RPT], au[RPT], av[RPT];
    #pragma unroll
    for (int k = 0; k < RPT; ++k) {
        float a0, a1;
        unpack2(se2[k], a0, a1); se[k] = a0 + a1;
        unpack2(au2[k], a0, a1); au[k] = a0 + a1;
        unpack2(av2[k], a0, a1); av[k] = a0 + a1;
    }

    // Publish segment partials (warps 1..3), combine in warp 0 (fixed order)
    if (warp > 0) {
        #pragma unroll
        for (int k = 0; k < RPT; ++k)
            sRow[warp - 1][lane + 32 * k] = make_float4(se[k], au[k], av[k], 0.0f);
    }
    __syncthreads();

    if (warp == 0) {
        float p[8];
        #pragma unroll
        for (int i = 0; i < 8; ++i) p[i] = 0.0f;

        #pragma unroll
        for (int k = 0; k < RPT; ++k) {
            float sek = se[k], auk = au[k], avk = av[k];
            #pragma unroll
            for (int q = 0; q < MSPLIT - 1; ++q) {   // fixed order seg1..3
                const float4 f = sRow[q][lane + 32 * k];
                sek += f.x; auk += f.y; avk += f.z;
            }
            const float KINV = 0.34657359027997264f; // ln(2)/2 (undo folded 2*log2e)
            const float inv = KINV / sek;
            const float tcx = auk * inv;
            const float tcy = avk * inv;
            // fixed-order accumulation over k
            p[0] += sx[k];        p[1] += sy[k];
            p[2] += tcx;          p[3] += tcy;
            p[4] += sx[k] * tcx;  p[5] += sx[k] * tcy;
            p[6] += sy[k] * tcx;  p[7] += sy[k] * tcy;
        }

        // Deterministic warp butterfly
        #pragma unroll
        for (int off = 16; off; off >>= 1)
            #pragma unroll
            for (int i = 0; i < 8; ++i)
                p[i] += __shfl_xor_sync(0xFFFFFFFFu, p[i], off);

        if (lane == 0) {
            #pragma unroll
            for (int i = 0; i < 8; ++i) g_part[b][chunk][i] = p[i];
        }
    }
}

// ---------------------------------------------------------------------------
// Final kernel: reduce last iteration's partials, compose T_5, write output.
// grid = BB x 32 threads. Reads T_4 from g_Tbuf[ITERS & 1] == g_Tbuf[1].
// ---------------------------------------------------------------------------
__global__ void icp_final_kernel(float* __restrict__ out) {
    const int b = blockIdx.x;
    const int t = threadIdx.x;

    float p[8];
    #pragma unroll
    for (int k = 0; k < 8; ++k) p[k] = g_part[b][t][k];
    #pragma unroll
    for (int off = 16; off; off >>= 1)
        #pragma unroll
        for (int k = 0; k < 8; ++k)
            p[k] += __shfl_xor_sync(0xFFFFFFFFu, p[k], off);

    if (t == 0) {
        const int rd = ITERS & 1;   // buffer holding T_{ITERS-1}
        float c2, s2, tx2, ty2;
        icp_compose(p, g_Tbuf[rd][b][0], g_Tbuf[rd][b][1],
                       g_Tbuf[rd][b][2], g_Tbuf[rd][b][3],
                    c2, s2, tx2, ty2);
        out[b * 3 + 0] = atan2f(s2, c2);
        out[b * 3 + 1] = tx2;
        out[b * 3 + 2] = ty2;
    }
}

// ---------------------------------------------------------------------------
extern "C" void kernel_launch(void* const* d_in, const int* in_sizes, int n_in,
                              void* d_out, int out_size) {
    const float* source = (const float*)d_in[0];   // (32, 2048, 2)
    const float* target = (const float*)d_in[1];   // (32, 2048, 2)
    const float* init_t = (const float*)d_in[2];   // (32, 3)
    float* out = (float*)d_out;                    // (32, 3)

    icp_init_kernel<<<(BB * NPAIR + 255) / 256, 256>>>(target, init_t);
    for (int it = 0; it < ITERS; ++it)
        icp_iter_kernel<<<BB * CHUNKS, TPB>>>(source, it);
    icp_final_kernel<<<BB, 32>>>(out);
}